// round 14
// baseline (speedup 1.0000x reference)
#include <cuda_runtime.h>
#include <cstdint>

// Gate_60421599920823 : MoE sigmoid gating via mma.sync bf16 2-way split.
//   logits = x[8192,4096] @ W^T[4096,64]  (fp32-equivalent: hh+hl+lh bf16 products,
//   split ONCE at load time into interleaved (h,l) smem tiles)
//   scores = sigmoid(logits); top-2 on (scores + bias); weights normalized.
// R13 (74.5us): phases serialized (store phase idles tensor pipe; 2 BAR/chunk).
// R14: fuse split_store + LDG prefetch INTO the compute phase; 1 BAR/chunk.
// Output: [weights N*2 | indices-as-float N*2 | scores N*64]

#define D_DIM    4096
#define NEXP     64
#define TILE_M   64
#define KC       64
#define NC       (D_DIM / KC)      // 64
#define THREADS  256
#define PITCHU   72                // u32 per packed row (64 data + 8 pad)
#define TILE_U32 (64 * PITCHU)     // 4608 u32 per tile (X or W)
#define BUF_U32  (2 * TILE_U32)    // X + W per stage
#define SMEM_TOTAL (2 * BUF_U32 * 4)   // 73728 B
#define C_STRIDE 68

// pack two floats' bf16 heads (f0 -> low half) and tails
__device__ __forceinline__ void split2(float f0, float f1, uint32_t& h, uint32_t& l) {
    asm("cvt.rn.bf16x2.f32 %0, %1, %2;" : "=r"(h) : "f"(f1), "f"(f0));
    float r0 = f0 - __uint_as_float(h << 16);
    float r1 = f1 - __uint_as_float(h & 0xFFFF0000u);
    asm("cvt.rn.bf16x2.f32 %0, %1, %2;" : "=r"(l) : "f"(r1), "f"(r0));
}
__device__ __forceinline__ void mma_bf16(float* d, const uint32_t* a, const uint32_t* b) {
    asm("mma.sync.aligned.m16n8k16.row.col.f32.bf16.bf16.f32 "
        "{%0,%1,%2,%3}, {%4,%5,%6,%7}, {%8,%9}, {%0,%1,%2,%3};"
        : "+f"(d[0]), "+f"(d[1]), "+f"(d[2]), "+f"(d[3])
        : "r"(a[0]), "r"(a[1]), "r"(a[2]), "r"(a[3]), "r"(b[0]), "r"(b[1]));
}

__global__ __launch_bounds__(THREADS, 1)
void gate_kernel(const float* __restrict__ x,
                 const float* __restrict__ w,
                 const float* __restrict__ bias,
                 float* __restrict__ out_w,
                 float* __restrict__ out_i,
                 float* __restrict__ out_s)
{
    extern __shared__ char smem[];
    uint32_t* Sp = (uint32_t*)smem;
    const int tid = threadIdx.x;
    const int row_base = blockIdx.x * TILE_M;

    const int lane = tid & 31;
    const int wid  = tid >> 5;         // 0..7
    const int wm   = wid & 3;          // m-tile: rows wm*16 .. +15
    const int wn   = wid >> 2;         // expert half
    const int g    = lane >> 2;        // 0..7
    const int q    = lane & 3;         // 0..3
    const int ar0  = wm * 16 + g;

    // per-thread gmem staging: 4 X float4 + 4 W float4 per chunk
    float4 xr[4], wr[4];
    int rr[4], cc[4];
    #pragma unroll
    for (int i = 0; i < 4; ++i) { int lin = tid + i * THREADS; rr[i] = lin >> 4; cc[i] = lin & 15; }

    auto load_gmem = [&](int c) {
        const int k0 = c * KC;
        #pragma unroll
        for (int i = 0; i < 4; ++i) {
            xr[i] = *(const float4*)(x + (size_t)(row_base + rr[i]) * D_DIM + k0 + cc[i] * 4);
            wr[i] = *(const float4*)(w + (size_t)rr[i] * D_DIM + k0 + cc[i] * 4);
        }
    };
    // split fp32 -> interleaved (h,l) bf16x2 pairs; one STS.128 per float4
    auto split_store = [&](int buf) {
        uint32_t* Xp = Sp + buf * BUF_U32;
        uint32_t* Wp = Xp + TILE_U32;
        #pragma unroll
        for (int i = 0; i < 4; ++i) {
            uint32_t h0, l0, h1, l1;
            split2(xr[i].x, xr[i].y, h0, l0);
            split2(xr[i].z, xr[i].w, h1, l1);
            *(uint4*)&Xp[rr[i] * PITCHU + cc[i] * 4] = make_uint4(h0, l0, h1, l1);
            split2(wr[i].x, wr[i].y, h0, l0);
            split2(wr[i].z, wr[i].w, h1, l1);
            *(uint4*)&Wp[rr[i] * PITCHU + cc[i] * 4] = make_uint4(h0, l0, h1, l1);
        }
    };

    // ---- mainloop: store/load fused with compute, 1 barrier per chunk ------
    float d[4][4];
    #pragma unroll
    for (int nt = 0; nt < 4; ++nt)
        #pragma unroll
        for (int i = 0; i < 4; ++i) d[nt][i] = 0.0f;

    load_gmem(0);
    split_store(0);                    // buf 0 = chunk 0
    load_gmem(1);                      // regs hold chunk 1
    __syncthreads();

    for (int c = 0; c < NC; ++c) {
        // stores for chunk c+1 go to buf (c+1)&1 — safe: compute(c-1) on that
        // buffer completed before the barrier ending iteration c-1.
        if (c + 1 < NC) split_store((c + 1) & 1);
        if (c + 2 < NC) load_gmem(c + 2);

        const uint32_t* Xp = Sp + (c & 1) * BUF_U32;
        const uint32_t* Wp = Xp + TILE_U32;

        #pragma unroll
        for (int ks = 0; ks < KC / 16; ++ks) {        // 4 k-steps of k=16
            const int ko = 16 * ks + 2 * q;           // u32 index of (h,l) pair
            const uint2 a0 = *(const uint2*)&Xp[ar0 * PITCHU + ko];
            const uint2 a1 = *(const uint2*)&Xp[(ar0 + 8) * PITCHU + ko];
            const uint2 a2 = *(const uint2*)&Xp[ar0 * PITCHU + ko + 8];
            const uint2 a3 = *(const uint2*)&Xp[(ar0 + 8) * PITCHU + ko + 8];
            const uint32_t Ah[4] = {a0.x, a1.x, a2.x, a3.x};
            const uint32_t Al[4] = {a0.y, a1.y, a2.y, a3.y};
            #pragma unroll
            for (int nt = 0; nt < 4; ++nt) {
                const int er = (wn * 32 + nt * 8 + g) * PITCHU + ko;
                const uint2 b0 = *(const uint2*)&Wp[er];
                const uint2 b1 = *(const uint2*)&Wp[er + 8];
                const uint32_t Bh[2] = {b0.x, b1.x};
                const uint32_t Bl[2] = {b0.y, b1.y};
                mma_bf16(d[nt], Ah, Bh);   // hh
                mma_bf16(d[nt], Ah, Bl);   // hl
                mma_bf16(d[nt], Al, Bh);   // lh
            }
        }
        __syncthreads();               // single barrier per chunk
    }

    // ---- epilogue: accumulators -> smem ------------------------------------
    float* C = (float*)smem;                          // [TILE_M][C_STRIDE]
    #pragma unroll
    for (int nt = 0; nt < 4; ++nt) {
        const int cb = wn * 32 + nt * 8 + q * 2;
        C[ar0 * C_STRIDE + cb + 0]       = d[nt][0];
        C[ar0 * C_STRIDE + cb + 1]       = d[nt][1];
        C[(ar0 + 8) * C_STRIDE + cb + 0] = d[nt][2];
        C[(ar0 + 8) * C_STRIDE + cb + 1] = d[nt][3];
    }
    __syncthreads();

    // sigmoid + coalesced scores store
    for (int idx = tid; idx < TILE_M * NEXP; idx += THREADS) {
        const int r = idx >> 6, e = idx & 63;
        const float v = 1.0f / (1.0f + __expf(-C[r * C_STRIDE + e]));
        C[r * C_STRIDE + e] = v;
        if (out_s) out_s[(size_t)row_base * NEXP + idx] = v;
    }
    __syncthreads();

    // per-row top-2 (strict > keeps lowest index on ties, like lax.top_k)
    if (tid < TILE_M) {
        const int r = tid;
        float b0 = -1e30f, b1 = -1e30f;
        int   i0 = 0,      i1 = 0;
        #pragma unroll
        for (int e = 0; e < NEXP; ++e) {
            const float v = C[r * C_STRIDE + e] + bias[e];
            if (v > b0)      { b1 = b0; i1 = i0; b0 = v; i0 = e; }
            else if (v > b1) { b1 = v;  i1 = e; }
        }
        const float w0 = C[r * C_STRIDE + i0];
        const float w1 = C[r * C_STRIDE + i1];
        const float inv = 1.0f / (w0 + w1);
        const int row = row_base + r;
        if (out_w) {
            out_w[row * 2 + 0] = w0 * inv;
            out_w[row * 2 + 1] = w1 * inv;
        }
        if (out_i) {
            out_i[row * 2 + 0] = (float)i0;
            out_i[row * 2 + 1] = (float)i1;
        }
    }
}

extern "C" void kernel_launch(void* const* d_in, const int* in_sizes, int n_in,
                              void* d_out, int out_size) {
    const float* x = (const float*)d_in[0];
    const float* w = (const float*)d_in[1];
    const float* b = (const float*)d_in[2];
    const int N = in_sizes[0] / D_DIM;         // 8192

    float* out = (float*)d_out;
    float* ow = nullptr; float* oi = nullptr; float* os = nullptr;
    if (out_size >= N * (2 * 2 + NEXP)) {      // full concat [w | i | s]
        ow = out; oi = out + (size_t)N * 2; os = out + (size_t)N * 4;
    } else if (out_size == N * NEXP) {
        os = out;
    } else if (out_size == N * 4) {
        ow = out; oi = out + (size_t)N * 2;
    } else {
        ow = out;
    }

    cudaFuncSetAttribute(gate_kernel, cudaFuncAttributeMaxDynamicSharedMemorySize, SMEM_TOTAL);
    gate_kernel<<<N / TILE_M, THREADS, SMEM_TOTAL>>>(x, w, b, ow, oi, os);
}